// round 8
// baseline (speedup 1.0000x reference)
#include <cuda_runtime.h>
#include <math.h>

#define HH 112
#define CC 32
#define W2 49
#define TOPK 4
#define KC 196
#define NW 256
#define HEADS 8
// 32^-0.5 * log2(e): softmax runs in log2 domain, ex2 instead of expf
#define SCALE_L2 0.25505654196908085f

#define KP_OFF 0        // Kp: 200 rows * 32, XOR-row-swizzled  (6400 floats)
#define VS_OFF 6400     // Vsw: 200 rows * 32, XOR-col-swizzled (6400 floats)
#define RO_OFF 12800    // rowOff: 196 ints
#define SM_TOT 12996    // floats -> 51984 B  (4 CTAs/SM)

__device__ __forceinline__ unsigned f2tf(float x) {
    unsigned r; asm("cvt.rna.tf32.f32 %0, %1;" : "=r"(r) : "f"(x)); return r;
}
__device__ __forceinline__ float tfbits(float x) {
    unsigned r = f2tf(x); return __uint_as_float(r);
}
__device__ __forceinline__ float ex2(float x) {
    float r; asm("ex2.approx.f32 %0, %1;" : "=f"(r) : "f"(x)); return r;
}
// NOTE: non-volatile — lets ptxas software-pipeline LDS/SHFL/HMMA across tiles.
__device__ __forceinline__ void mma_tf32(float* cc,
                                         unsigned a0, unsigned a1, unsigned a2, unsigned a3,
                                         unsigned b0, unsigned b1) {
    asm("mma.sync.aligned.m16n8k8.row.col.f32.tf32.tf32.f32 "
        "{%0,%1,%2,%3}, {%4,%5,%6,%7}, {%8,%9}, {%0,%1,%2,%3};"
        : "+f"(cc[0]), "+f"(cc[1]), "+f"(cc[2]), "+f"(cc[3])
        : "r"(a0), "r"(a1), "r"(a2), "r"(a3), "r"(b0), "r"(b1));
}

// C-fragment (rows r0/r1, cols 2c,2c+1 per 8-col tile) -> A-fragment for PV.
// P passed as raw fp32 bits; tf32 MMA truncates (RZ) — acceptable for P in [0,1].
__device__ __forceinline__ void frag_from_C(const float* pv, int lane, int c,
                                            unsigned& A0, unsigned& A1,
                                            unsigned& A2, unsigned& A3) {
    int src1 = (lane & 28) | (c >> 1);
    int src2 = src1 + 2;
    float u0 = __shfl_sync(0xffffffffu, pv[0], src1);
    float u1 = __shfl_sync(0xffffffffu, pv[1], src1);
    float u2 = __shfl_sync(0xffffffffu, pv[2], src1);
    float u3 = __shfl_sync(0xffffffffu, pv[3], src1);
    float w0 = __shfl_sync(0xffffffffu, pv[0], src2);
    float w1 = __shfl_sync(0xffffffffu, pv[1], src2);
    float w2 = __shfl_sync(0xffffffffu, pv[2], src2);
    float w3 = __shfl_sync(0xffffffffu, pv[3], src2);
    bool odd = (c & 1);
    A0 = __float_as_uint(odd ? u1 : u0);
    A1 = __float_as_uint(odd ? u3 : u2);
    A2 = __float_as_uint(odd ? w1 : w0);
    A3 = __float_as_uint(odd ? w3 : w2);
}

// Process score tiles [T0, T0+NT) with online softmax (log2 domain) into o/M/S.
template<int T0, int NT, bool ODD, bool MASK, bool FIRST>
__device__ __forceinline__ void do_chunk(
    const float* __restrict__ Kp, const float* __restrict__ Vsw,
    const unsigned* qa, int lane, int g, int c,
    float o[4][4], float& M0, float& M1, float& S0, float& S1)
{
    float acc[NT][4];
    #pragma unroll
    for (int nt = 0; nt < NT; nt++) {
        int krow = (T0 + nt)*8 + g;
        const float* kr = Kp + krow*32;
        int sw = (krow & 7) << 2;
        uint4 kb0 = *(const uint4*)(kr + ((c*8) ^ sw));
        uint4 kb1 = *(const uint4*)(kr + ((c*8 + 4) ^ sw));
        acc[nt][0] = acc[nt][1] = acc[nt][2] = acc[nt][3] = 0.f;
        mma_tf32(acc[nt], qa[0],  qa[1],  qa[2],  qa[3],  kb0.x, kb0.y);
        mma_tf32(acc[nt], qa[4],  qa[5],  qa[6],  qa[7],  kb0.z, kb0.w);
        mma_tf32(acc[nt], qa[8],  qa[9],  qa[10], qa[11], kb1.x, kb1.y);
        mma_tf32(acc[nt], qa[12], qa[13], qa[14], qa[15], kb1.z, kb1.w);
    }
    if (MASK) {
        if (c >= 2) { acc[NT-1][0] = acc[NT-1][1] = acc[NT-1][2] = acc[NT-1][3] = -INFINITY; }
    }
    // chunk max
    float cm0 = -INFINITY, cm1 = -INFINITY;
    #pragma unroll
    for (int nt = 0; nt < NT; nt++) {
        cm0 = fmaxf(cm0, fmaxf(acc[nt][0], acc[nt][1]));
        cm1 = fmaxf(cm1, fmaxf(acc[nt][2], acc[nt][3]));
    }
    cm0 = fmaxf(cm0, __shfl_xor_sync(0xffffffffu, cm0, 1));
    cm0 = fmaxf(cm0, __shfl_xor_sync(0xffffffffu, cm0, 2));
    cm1 = fmaxf(cm1, __shfl_xor_sync(0xffffffffu, cm1, 1));
    cm1 = fmaxf(cm1, __shfl_xor_sync(0xffffffffu, cm1, 2));
    float Mn0, Mn1;
    if (FIRST) { Mn0 = cm0; Mn1 = cm1; }
    else {
        Mn0 = fmaxf(M0, cm0); Mn1 = fmaxf(M1, cm1);
        float e0 = ex2(M0 - Mn0), e1 = ex2(M1 - Mn1);
        S0 *= e0; S1 *= e1;
        #pragma unroll
        for (int n4 = 0; n4 < 4; n4++) {
            o[n4][0] *= e0; o[n4][1] *= e0;
            o[n4][2] *= e1; o[n4][3] *= e1;
        }
    }
    float s0 = 0.f, s1 = 0.f;
    #pragma unroll
    for (int nt = 0; nt < NT; nt++) {
        acc[nt][0] = ex2(acc[nt][0] - Mn0);
        acc[nt][1] = ex2(acc[nt][1] - Mn0);
        acc[nt][2] = ex2(acc[nt][2] - Mn1);
        acc[nt][3] = ex2(acc[nt][3] - Mn1);
        s0 += acc[nt][0] + acc[nt][1];
        s1 += acc[nt][2] + acc[nt][3];
    }
    s0 += __shfl_xor_sync(0xffffffffu, s0, 1);
    s0 += __shfl_xor_sync(0xffffffffu, s0, 2);
    s1 += __shfl_xor_sync(0xffffffffu, s1, 1);
    s1 += __shfl_xor_sync(0xffffffffu, s1, 2);
    if (FIRST) { S0 = s0; S1 = s1; } else { S0 += s0; S1 += s1; }
    M0 = Mn0; M1 = Mn1;

    // PV: transpose C->A fragments; B from col-swizzled row-major Vsw (scalar LDS,
    // conflict-free: bank = g + 8*(n4^c), all 32 lanes distinct).
    #pragma unroll
    for (int p2 = 0; p2 < NT/2; p2++) {
        unsigned A00, A01, A02, A03, A10, A11, A12, A13;
        frag_from_C(acc[2*p2],     lane, c, A00, A01, A02, A03);
        frag_from_C(acc[2*p2 + 1], lane, c, A10, A11, A12, A13);
        int ktp = T0/2 + p2;
        const float* rp = Vsw + (16*ktp + c)*32 + g;
        #pragma unroll
        for (int n4 = 0; n4 < 4; n4++) {
            int co = 8*(n4 ^ c);
            float b0 = rp[co];
            float b1 = rp[co + 128];
            float b2 = rp[co + 256];
            float b3 = rp[co + 384];
            mma_tf32(o[n4], A00, A01, A02, A03,
                     __float_as_uint(b0), __float_as_uint(b1));
            mma_tf32(o[n4], A10, A11, A12, A13,
                     __float_as_uint(b2), __float_as_uint(b3));
        }
    }
    if (ODD) {
        unsigned A0, A1, A2, A3;
        frag_from_C(acc[NT-1], lane, c, A0, A1, A2, A3);
        const float* rp = Vsw + ((T0 + NT - 1)*8 + c)*32 + g;
        #pragma unroll
        for (int n4 = 0; n4 < 4; n4++) {
            int co = 8*(n4 ^ c);
            float b0 = rp[co];
            float b1 = rp[co + 128];
            mma_tf32(o[n4], A0, A1, A2, A3,
                     __float_as_uint(b0), __float_as_uint(b1));
        }
    }
}

__global__ __launch_bounds__(128, 4)
void wsa_kernel(const float* __restrict__ q, const float* __restrict__ k,
                const float* __restrict__ v, const int* __restrict__ indices,
                float* __restrict__ out)
{
    extern __shared__ float sm[];
    float* Kp  = sm + KP_OFF;
    float* Vsw = sm + VS_OFF;
    int* rowOff = (int*)(sm + RO_OFF);

    const int w = blockIdx.x;
    const int h = blockIdx.y;
    const int b = blockIdx.z;
    const int t = threadIdx.x;
    const int wy = w >> 4, wx = w & 15;

    const size_t base = ((size_t)(b*HEADS + h)) * (size_t)(HH*HH*CC);
    const float* qb = q + base;
    const float* kb = k + base;
    const float* vb = v + base;
    const int idxBase = ((b*HEADS + h)*NW + w)*TOPK;

    const int lane = t & 31, warp = t >> 5;
    const int g = lane >> 2, c = lane & 3;
    const int r0 = warp*16 + g, r1 = r0 + 8;
    const bool w0v = (r0 < W2), w1v = (r1 < W2);

    // ---- rowOff table (indices via cached LDG) ----
    for (int row = t; row < KC; row += 128) {
        int tt = (row * 21401) >> 20;           // row / 49
        int p  = row - tt*W2;
        int ws = __ldg(indices + idxBase + tt);
        int p7 = (p * 9363) >> 16;              // p / 7
        int y = (ws >> 4)*7 + p7;
        int x = (ws & 15)*7 + (p - p7*7);
        rowOff[row] = (y*HH + x)*CC;
    }
    // ---- zero V pad rows 196-199 (avoid 0*garbage = NaN in PV) ----
    if (t < 128) Vsw[196*32 + t] = 0.f;

    // ---- Q: coalesced LDG -> per-warp smem staging (overlaid on Kp) -> frags ----
    unsigned qa[16];
    {
        float* Qst = sm + warp*576;             // 16 rows * 36, inside Kp region
        #pragma unroll
        for (int a = 0; a < 4; a++) {
            int j = 4*a + (lane >> 3);          // 0..15
            int p = warp*16 + j;
            int c4g = lane & 7;
            float4 qq = make_float4(0.f, 0.f, 0.f, 0.f);
            if (p < W2) {
                int p7 = (p * 9363) >> 16;
                int y = wy*7 + p7, x = wx*7 + (p - p7*7);
                qq = *(const float4*)(qb + (y*HH + x)*CC + 4*c4g);
            }
            float* qd = Qst + j*36 + 4*c4g;
            qd[0] = tfbits(qq.x * SCALE_L2);
            qd[1] = tfbits(qq.y * SCALE_L2);
            qd[2] = tfbits(qq.z * SCALE_L2);
            qd[3] = tfbits(qq.w * SCALE_L2);
        }
        __syncwarp();
        #pragma unroll
        for (int kt = 0; kt < 4; kt++) {
            qa[kt*4+0] = __float_as_uint(Qst[g*36     + kt*8 + c]);
            qa[kt*4+1] = __float_as_uint(Qst[(8+g)*36 + kt*8 + c]);
            qa[kt*4+2] = __float_as_uint(Qst[g*36     + kt*8 + c + 4]);
            qa[kt*4+3] = __float_as_uint(Qst[(8+g)*36 + kt*8 + c + 4]);
        }
    }
    __syncthreads();   // Q frags read; rowOff visible; gathers may overwrite

    // ---- K gather: row-major LDG (4 lines/warp), XOR-row-swizzled store ----
    for (int i = t; i < 1568; i += 128) {
        int row = i >> 3, c4g = i & 7;
        float4 kk = *(const float4*)(kb + rowOff[row] + 4*c4g);
        float* kr = Kp + row*32;
        int sw = (row & 7) << 2;
        kr[(c4g)      ^ sw] = tfbits(kk.x);
        kr[(c4g + 8)  ^ sw] = tfbits(kk.y);
        kr[(c4g + 16) ^ sw] = tfbits(kk.z);
        kr[(c4g + 24) ^ sw] = tfbits(kk.w);
    }
    // ---- V gather: row-major LDG, col-XOR-swizzled float4 store (conflict-free) ----
    for (int i = t; i < 1568; i += 128) {
        int row = i >> 3, c4g = i & 7;
        float4 vv = *(const float4*)(vb + rowOff[row] + 4*c4g);
        float* vr = Vsw + row*32 + ((4*c4g) ^ ((row & 3) << 3));
        vr[0] = tfbits(vv.x);
        vr[1] = tfbits(vv.y);
        vr[2] = tfbits(vv.z);
        vr[3] = tfbits(vv.w);
    }
    __syncthreads();

    // ======== per-warp flash attention over two N-chunks ========
    float o[4][4] = {};
    float M0, M1, S0, S1;
    do_chunk<0, 12, false, false, true >(Kp, Vsw, qa, lane, g, c, o, M0, M1, S0, S1);
    do_chunk<12, 13, true,  true,  false>(Kp, Vsw, qa, lane, g, c, o, M0, M1, S0, S1);

    // ---- epilogue: normalize + store out[b, y, x, h*32 + col] ----
    {
        float i0 = 1.0f / S0;
        float i1 = 1.0f / S1;
        float* ob = out + ((size_t)b*(HH*HH))*256 + h*CC;
        int p70 = (r0 * 9363) >> 16;
        int p71 = (r1 * 9363) >> 16;
        int y0 = wy*7 + p70, x0 = wx*7 + (r0 - p70*7);
        int y1 = wy*7 + p71, x1 = wx*7 + (r1 - p71*7);
        float* ob0 = ob + (size_t)(y0*HH + x0)*256;
        float* ob1 = ob + (size_t)(y1*HH + x1)*256;
        #pragma unroll
        for (int n4 = 0; n4 < 4; n4++) {
            int colb = n4*8 + 2*c;
            if (w0v) *(float2*)(ob0 + colb) = make_float2(o[n4][0]*i0, o[n4][1]*i0);
            if (w1v) *(float2*)(ob1 + colb) = make_float2(o[n4][2]*i1, o[n4][3]*i1);
        }
    }
}

extern "C" void kernel_launch(void* const* d_in, const int* in_sizes, int n_in,
                              void* d_out, int out_size)
{
    const float* q   = (const float*)d_in[0];
    const float* k   = (const float*)d_in[1];
    const float* v   = (const float*)d_in[2];
    const int*   idx = (const int*)d_in[3];
    float* out = (float*)d_out;

    int smem = SM_TOT * (int)sizeof(float);   // 51984 B -> 4 CTAs/SM
    cudaFuncSetAttribute(wsa_kernel, cudaFuncAttributeMaxDynamicSharedMemorySize, smem);

    dim3 grid(NW, HEADS, 4);
    wsa_kernel<<<grid, 128, smem>>>(q, k, v, idx, out);
}

// round 9
// speedup vs baseline: 1.8548x; 1.8548x over previous
#include <cuda_runtime.h>
#include <math.h>

#define HH 112
#define CC 32
#define W2 49
#define TOPK 4
#define KC 196
#define NW 256
#define HEADS 8
// 32^-0.5 * log2(e): softmax in log2 domain
#define SCALE_L2 0.25505654196908085f

#define KP_OFF 0        // Kp: 200 rows * 32, 16B-granular XOR row swizzle (6400 floats)
#define VS_OFF 6400     // Vsw: 200 rows * 32, XOR-col swizzle           (6400 floats)
#define SM_TOT 12800    // floats -> 51200 B (4 CTAs/SM)

__device__ __forceinline__ float tfbits(float x) {
    unsigned r; asm("cvt.rna.tf32.f32 %0, %1;" : "=r"(r) : "f"(x));
    return __uint_as_float(r);
}
__device__ __forceinline__ float ex2(float x) {
    float r; asm("ex2.approx.f32 %0, %1;" : "=f"(r) : "f"(x)); return r;
}
__device__ __forceinline__ void cp16(unsigned dst, const void* src) {
    asm volatile("cp.async.cg.shared.global [%0], [%1], 16;" :: "r"(dst), "l"(src));
}
// non-volatile: ptxas may pipeline LDS/SHFL/HMMA freely
__device__ __forceinline__ void mma_tf32(float* cc,
                                         unsigned a0, unsigned a1, unsigned a2, unsigned a3,
                                         unsigned b0, unsigned b1) {
    asm("mma.sync.aligned.m16n8k8.row.col.f32.tf32.tf32.f32 "
        "{%0,%1,%2,%3}, {%4,%5,%6,%7}, {%8,%9}, {%0,%1,%2,%3};"
        : "+f"(cc[0]), "+f"(cc[1]), "+f"(cc[2]), "+f"(cc[3])
        : "r"(a0), "r"(a1), "r"(a2), "r"(a3), "r"(b0), "r"(b1));
}

// C-fragment -> A-fragment for PV (raw fp32 bits; MMA RZ-truncates, P in [0,1]).
__device__ __forceinline__ void frag_from_C(const float* pv, int lane, int c,
                                            unsigned& A0, unsigned& A1,
                                            unsigned& A2, unsigned& A3) {
    int src1 = (lane & 28) | (c >> 1);
    int src2 = src1 + 2;
    float u0 = __shfl_sync(0xffffffffu, pv[0], src1);
    float u1 = __shfl_sync(0xffffffffu, pv[1], src1);
    float u2 = __shfl_sync(0xffffffffu, pv[2], src1);
    float u3 = __shfl_sync(0xffffffffu, pv[3], src1);
    float w0 = __shfl_sync(0xffffffffu, pv[0], src2);
    float w1 = __shfl_sync(0xffffffffu, pv[1], src2);
    float w2 = __shfl_sync(0xffffffffu, pv[2], src2);
    float w3 = __shfl_sync(0xffffffffu, pv[3], src2);
    bool odd = (c & 1);
    A0 = __float_as_uint(odd ? u1 : u0);
    A1 = __float_as_uint(odd ? u3 : u2);
    A2 = __float_as_uint(odd ? w1 : w0);
    A3 = __float_as_uint(odd ? w3 : w2);
}

__device__ __forceinline__ int row_off(int row, const int* __restrict__ idxp) {
    int tt = (row * 21401) >> 20;           // row / 49
    int p  = row - tt*W2;
    int ws = __ldg(idxp + tt);
    int p7 = (p * 9363) >> 16;              // p / 7
    int y = (ws >> 4)*7 + p7;
    int x = (ws & 15)*7 + (p - p7*7);
    return (y*HH + x)*CC;
}

// Score tiles [T0, T0+NT) with online softmax (log2 domain) into o/M/S.
template<int T0, int NT, bool ODD, bool MASK, bool FIRST>
__device__ __forceinline__ void do_chunk(
    const float* __restrict__ Kp, const float* __restrict__ Vsw,
    const unsigned* qa, int lane, int g, int c,
    float o[4][4], float& M0, float& M1, float& S0, float& S1)
{
    float acc[NT][4];
    #pragma unroll
    for (int nt = 0; nt < NT; nt++) {
        int krow = (T0 + nt)*8 + g;
        const float* kr = Kp + krow*32 + c;    // scalar frag loads, conflict-free
        int sw = (krow & 7) << 2;
        acc[nt][0] = acc[nt][1] = acc[nt][2] = acc[nt][3] = 0.f;
        mma_tf32(acc[nt], qa[0],  qa[1],  qa[2],  qa[3],
                 __float_as_uint(kr[0 ^ sw]),  __float_as_uint(kr[4 ^ sw]));
        mma_tf32(acc[nt], qa[4],  qa[5],  qa[6],  qa[7],
                 __float_as_uint(kr[8 ^ sw]),  __float_as_uint(kr[12 ^ sw]));
        mma_tf32(acc[nt], qa[8],  qa[9],  qa[10], qa[11],
                 __float_as_uint(kr[16 ^ sw]), __float_as_uint(kr[20 ^ sw]));
        mma_tf32(acc[nt], qa[12], qa[13], qa[14], qa[15],
                 __float_as_uint(kr[24 ^ sw]), __float_as_uint(kr[28 ^ sw]));
    }
    if (MASK) {
        if (c >= 2) { acc[NT-1][0] = acc[NT-1][1] = acc[NT-1][2] = acc[NT-1][3] = -INFINITY; }
    }
    float cm0 = -INFINITY, cm1 = -INFINITY;
    #pragma unroll
    for (int nt = 0; nt < NT; nt++) {
        cm0 = fmaxf(cm0, fmaxf(acc[nt][0], acc[nt][1]));
        cm1 = fmaxf(cm1, fmaxf(acc[nt][2], acc[nt][3]));
    }
    cm0 = fmaxf(cm0, __shfl_xor_sync(0xffffffffu, cm0, 1));
    cm0 = fmaxf(cm0, __shfl_xor_sync(0xffffffffu, cm0, 2));
    cm1 = fmaxf(cm1, __shfl_xor_sync(0xffffffffu, cm1, 1));
    cm1 = fmaxf(cm1, __shfl_xor_sync(0xffffffffu, cm1, 2));
    float Mn0, Mn1;
    if (FIRST) { Mn0 = cm0; Mn1 = cm1; }
    else {
        Mn0 = fmaxf(M0, cm0); Mn1 = fmaxf(M1, cm1);
        float e0 = ex2(M0 - Mn0), e1 = ex2(M1 - Mn1);
        S0 *= e0; S1 *= e1;
        #pragma unroll
        for (int n4 = 0; n4 < 4; n4++) {
            o[n4][0] *= e0; o[n4][1] *= e0;
            o[n4][2] *= e1; o[n4][3] *= e1;
        }
    }
    float s0 = 0.f, s1 = 0.f;
    #pragma unroll
    for (int nt = 0; nt < NT; nt++) {
        acc[nt][0] = ex2(acc[nt][0] - Mn0);
        acc[nt][1] = ex2(acc[nt][1] - Mn0);
        acc[nt][2] = ex2(acc[nt][2] - Mn1);
        acc[nt][3] = ex2(acc[nt][3] - Mn1);
        s0 += acc[nt][0] + acc[nt][1];
        s1 += acc[nt][2] + acc[nt][3];
    }
    s0 += __shfl_xor_sync(0xffffffffu, s0, 1);
    s0 += __shfl_xor_sync(0xffffffffu, s0, 2);
    s1 += __shfl_xor_sync(0xffffffffu, s1, 1);
    s1 += __shfl_xor_sync(0xffffffffu, s1, 2);
    if (FIRST) { S0 = s0; S1 = s1; } else { S0 += s0; S1 += s1; }
    M0 = Mn0; M1 = Mn1;

    // PV: B from col-swizzled row-major Vsw (scalar LDS, conflict-free)
    #pragma unroll
    for (int p2 = 0; p2 < NT/2; p2++) {
        unsigned A00, A01, A02, A03, A10, A11, A12, A13;
        frag_from_C(acc[2*p2],     lane, c, A00, A01, A02, A03);
        frag_from_C(acc[2*p2 + 1], lane, c, A10, A11, A12, A13);
        int ktp = T0/2 + p2;
        const float* rp = Vsw + (16*ktp + c)*32 + g;
        #pragma unroll
        for (int n4 = 0; n4 < 4; n4++) {
            int co = 8*(n4 ^ c);
            float b0 = rp[co];
            float b1 = rp[co + 128];
            float b2 = rp[co + 256];
            float b3 = rp[co + 384];
            mma_tf32(o[n4], A00, A01, A02, A03,
                     __float_as_uint(b0), __float_as_uint(b1));
            mma_tf32(o[n4], A10, A11, A12, A13,
                     __float_as_uint(b2), __float_as_uint(b3));
        }
    }
    if (ODD) {
        unsigned A0, A1, A2, A3;
        frag_from_C(acc[NT-1], lane, c, A0, A1, A2, A3);
        const float* rp = Vsw + ((T0 + NT - 1)*8 + c)*32 + g;
        #pragma unroll
        for (int n4 = 0; n4 < 4; n4++) {
            int co = 8*(n4 ^ c);
            float b0 = rp[co];
            float b1 = rp[co + 128];
            mma_tf32(o[n4], A0, A1, A2, A3,
                     __float_as_uint(b0), __float_as_uint(b1));
        }
    }
}

__global__ __launch_bounds__(128, 4)
void wsa_kernel(const float* __restrict__ q, const float* __restrict__ k,
                const float* __restrict__ v, const int* __restrict__ indices,
                float* __restrict__ out)
{
    extern __shared__ float sm[];
    float* Kp  = sm + KP_OFF;
    float* Vsw = sm + VS_OFF;

    const int w = blockIdx.x;
    const int h = blockIdx.y;
    const int b = blockIdx.z;
    const int t = threadIdx.x;
    const int wy = w >> 4, wx = w & 15;

    const size_t base = ((size_t)(b*HEADS + h)) * (size_t)(HH*HH*CC);
    const float* qb = q + base;
    const float* kb = k + base;
    const float* vb = v + base;
    const int* idxp = indices + ((b*HEADS + h)*NW + w)*TOPK;

    const int lane = t & 31, warp = t >> 5;
    const int g = lane >> 2, c = lane & 3;
    const int r0 = warp*16 + g, r1 = r0 + 8;
    const bool w0v = (r0 < W2), w1v = (r1 < W2);

    const unsigned smem_u32 = (unsigned)__cvta_generic_to_shared(sm);
    const unsigned kp_u32 = smem_u32;
    const unsigned vs_u32 = smem_u32 + VS_OFF*4;

    // ---- 1) K gather via cp.async (inline offsets; Kp region untouched by Q) ----
    {
        int c4 = (t & 7) << 2;
        #pragma unroll
        for (int m = 0; m < 13; m++) {
            int i = t + 128*m;
            if (i < 1568) {
                int row = i >> 3;
                int off = row_off(row, idxp);
                unsigned dst = kp_u32 + (row*32 + (c4 ^ ((row & 7) << 2)))*4;
                cp16(dst, kb + off + c4);
            }
        }
        asm volatile("cp.async.commit_group;");
    }

    // ---- 2) Q stage (overlaid on Vsw; overlaps K cp.async flight) ----
    unsigned qa[16];
    {
        float* Qst = Vsw + warp*576;            // 16 rows * 36
        #pragma unroll
        for (int a = 0; a < 4; a++) {
            int j = 4*a + (lane >> 3);
            int p = warp*16 + j;
            int c4g = lane & 7;
            float4 qq = make_float4(0.f, 0.f, 0.f, 0.f);
            if (p < W2) {
                int p7 = (p * 9363) >> 16;
                int y = wy*7 + p7, x = wx*7 + (p - p7*7);
                qq = *(const float4*)(qb + (y*HH + x)*CC + 4*c4g);
            }
            float* qd = Qst + j*36 + 4*c4g;
            qd[0] = tfbits(qq.x * SCALE_L2);
            qd[1] = tfbits(qq.y * SCALE_L2);
            qd[2] = tfbits(qq.z * SCALE_L2);
            qd[3] = tfbits(qq.w * SCALE_L2);
        }
        __syncwarp();
        #pragma unroll
        for (int kt = 0; kt < 4; kt++) {
            qa[kt*4+0] = __float_as_uint(Qst[g*36     + kt*8 + c]);
            qa[kt*4+1] = __float_as_uint(Qst[(8+g)*36 + kt*8 + c]);
            qa[kt*4+2] = __float_as_uint(Qst[g*36     + kt*8 + c + 4]);
            qa[kt*4+3] = __float_as_uint(Qst[(8+g)*36 + kt*8 + c + 4]);
        }
    }
    __syncthreads();    // all Q frags read -> Vsw region free for V

    // ---- 3) V pad zero + V gather via cp.async ----
    if (t < 128) Vsw[196*32 + t] = 0.f;
    {
        int c4 = (t & 7) << 2;
        #pragma unroll
        for (int m = 0; m < 13; m++) {
            int i = t + 128*m;
            if (i < 1568) {
                int row = i >> 3;
                int off = row_off(row, idxp);
                unsigned dst = vs_u32 + (row*32 + (c4 ^ ((row & 3) << 3)))*4;
                cp16(dst, vb + off + c4);
            }
        }
        asm volatile("cp.async.commit_group;");
    }
    asm volatile("cp.async.wait_group 0;" ::: "memory");
    __syncthreads();

    // ======== per-warp flash attention over two N-chunks ========
    float o[4][4] = {};
    float M0, M1, S0, S1;
    do_chunk<0, 12, false, false, true >(Kp, Vsw, qa, lane, g, c, o, M0, M1, S0, S1);
    do_chunk<12, 13, true,  true,  false>(Kp, Vsw, qa, lane, g, c, o, M0, M1, S0, S1);

    // ---- epilogue ----
    {
        float i0 = 1.0f / S0;
        float i1 = 1.0f / S1;
        float* ob = out + ((size_t)b*(HH*HH))*256 + h*CC;
        int p70 = (r0 * 9363) >> 16;
        int p71 = (r1 * 9363) >> 16;
        int y0 = wy*7 + p70, x0 = wx*7 + (r0 - p70*7);
        int y1 = wy*7 + p71, x1 = wx*7 + (r1 - p71*7);
        float* ob0 = ob + (size_t)(y0*HH + x0)*256;
        float* ob1 = ob + (size_t)(y1*HH + x1)*256;
        #pragma unroll
        for (int n4 = 0; n4 < 4; n4++) {
            int colb = n4*8 + 2*c;
            if (w0v) *(float2*)(ob0 + colb) = make_float2(o[n4][0]*i0, o[n4][1]*i0);
            if (w1v) *(float2*)(ob1 + colb) = make_float2(o[n4][2]*i1, o[n4][3]*i1);
        }
    }
}

extern "C" void kernel_launch(void* const* d_in, const int* in_sizes, int n_in,
                              void* d_out, int out_size)
{
    const float* q   = (const float*)d_in[0];
    const float* k   = (const float*)d_in[1];
    const float* v   = (const float*)d_in[2];
    const int*   idx = (const int*)d_in[3];
    float* out = (float*)d_out;

    int smem = SM_TOT * (int)sizeof(float);   // 51200 B -> 4 CTAs/SM
    cudaFuncSetAttribute(wsa_kernel, cudaFuncAttributeMaxDynamicSharedMemorySize, smem);

    dim3 grid(NW, HEADS, 4);
    wsa_kernel<<<grid, 128, smem>>>(q, k, v, idx, out);
}